// round 4
// baseline (speedup 1.0000x reference)
#include <cuda_runtime.h>
#include <math.h>

#define SEQ    4096
#define NH     16
#define HD     80
#define HIDDEN 1280
#define QKVN   3840
#define INV_SCALE 0.11180339887498948f   // 1/sqrt(80)

// -------- scratch (no allocation allowed -> __device__ globals) --------
__device__ float g_qkv [SEQ * QKVN];    // 62.9 MB : [seq][3*hidden]
__device__ float g_attn[SEQ * HIDDEN];  // 21.0 MB : attention output

// =====================================================================
// SGEMM: C[M,N] = A[M,K] @ B[K,N] + bias[N]
// 128x128 tile, BK=8, 256 threads, 8x8 micro-tile.
// =====================================================================
__global__ void __launch_bounds__(256)
sgemm_bias(const float* __restrict__ A, const float* __restrict__ B,
           const float* __restrict__ bias, float* __restrict__ C,
           int M, int N, int K)
{
    const int BM = 128, BN = 128, BK = 8, TM = 8, TN = 8;
    __shared__ float As[BK][BM];
    __shared__ float Bs[BK][BN];

    int tid = threadIdx.x;
    int tx = tid % 16;
    int ty = tid / 16;
    int bx = blockIdx.x, by = blockIdx.y;

    const float* Ab = A + (size_t)by * BM * K;
    const float* Bb = B + (size_t)bx * BN;

    int arow = tid >> 1;
    int acol = (tid & 1) * 4;
    int brow = tid >> 5;
    int bcol = (tid & 31) * 4;

    float acc[TM][TN];
    #pragma unroll
    for (int i = 0; i < TM; i++)
        #pragma unroll
        for (int j = 0; j < TN; j++) acc[i][j] = 0.f;

    for (int k0 = 0; k0 < K; k0 += BK) {
        float4 a4 = *(const float4*)&Ab[(size_t)arow * K + k0 + acol];
        As[acol + 0][arow] = a4.x;
        As[acol + 1][arow] = a4.y;
        As[acol + 2][arow] = a4.z;
        As[acol + 3][arow] = a4.w;
        float4 b4 = *(const float4*)&Bb[(size_t)(k0 + brow) * N + bcol];
        *(float4*)&Bs[brow][bcol] = b4;
        __syncthreads();

        #pragma unroll
        for (int k = 0; k < BK; k++) {
            float ra[TM], rb[TN];
            *(float4*)&ra[0] = *(const float4*)&As[k][ty * TM];
            *(float4*)&ra[4] = *(const float4*)&As[k][ty * TM + 4];
            *(float4*)&rb[0] = *(const float4*)&Bs[k][tx * TN];
            *(float4*)&rb[4] = *(const float4*)&Bs[k][tx * TN + 4];
            #pragma unroll
            for (int i = 0; i < TM; i++)
                #pragma unroll
                for (int j = 0; j < TN; j++)
                    acc[i][j] = fmaf(ra[i], rb[j], acc[i][j]);
        }
        __syncthreads();
    }

    #pragma unroll
    for (int i = 0; i < TM; i++) {
        size_t row = (size_t)by * BM + ty * TM + i;
        #pragma unroll
        for (int j = 0; j < TN; j += 4) {
            int col = bx * BN + tx * TN + j;
            float4 c4;
            c4.x = acc[i][j + 0] + bias[col + 0];
            c4.y = acc[i][j + 1] + bias[col + 1];
            c4.z = acc[i][j + 2] + bias[col + 2];
            c4.w = acc[i][j + 3] + bias[col + 3];
            *(float4*)&C[row * N + col] = c4;
        }
    }
}

// =====================================================================
// RoPE in-place on Q and K halves of g_qkv.
// =====================================================================
__global__ void rope_kernel(const float* __restrict__ cosE,
                            const float* __restrict__ sinE)
{
    int idx = blockIdx.x * blockDim.x + threadIdx.x;
    const int TOT = 2 * SEQ * NH * (HD / 2);
    if (idx >= TOT) return;
    int d    = idx % 40;
    int h    = (idx / 40) % NH;
    int s    = (idx / (40 * NH)) % SEQ;
    int part = idx / (40 * NH * SEQ);

    float* p = g_qkv + (size_t)s * QKVN + part * HIDDEN + h * HD;
    float t1 = p[d], t2 = p[d + 40];
    float c1 = cosE[s * HD + d],      s1 = sinE[s * HD + d];
    float c2 = cosE[s * HD + d + 40], s2 = sinE[s * HD + d + 40];
    p[d]      = t1 * c1 - t2 * s1;
    p[d + 40] = t2 * c2 + t1 * s2;
}

// =====================================================================
// Flash attention v2: BM=128 x BN=128 tile, 8x8 micro-tile, 256 threads.
// Qt/Kt dim-major [HD][128+pad]; Vs key-major [128][84];
// Ss (P tile) row-major [128][128].
// Row group = 16 contiguous lanes (half warp) -> shfl reductions + syncwarp.
// =====================================================================
#define FBM 128
#define FBN 128
#define FRP 132                       // pad for Qt/Kt rows (128 -> 132)
#define FVP 84                        // pad for Vs rows (80 -> 84)
#define FA2_SMEM_FLOATS (HD*FRP + HD*FRP + FBN*FVP + FBM*FBN)
#define FA2_SMEM_BYTES  (FA2_SMEM_FLOATS * 4)

__global__ void __launch_bounds__(256, 1)
flash_attn_kernel()
{
    extern __shared__ float sm[];
    float* Qt = sm;                    // [HD][FRP]
    float* Kt = Qt + HD * FRP;         // [HD][FRP]
    float* Vs = Kt + HD * FRP;         // [FBN][FVP]
    float* Ss = Vs + FBN * FVP;        // [FBM][FBN]

    int tid = threadIdx.x;
    int tc  = tid % 16;                // col group (8 cols / 5 dims)
    int tr  = tid / 16;                // row group (8 rows)
    int h   = blockIdx.y;
    int q0  = blockIdx.x * FBM;

    // ---- load Q tile transposed, pre-scaled. c-major lane map:
    // consecutive lanes -> consecutive q rows -> conflict-free STS.
    const float* qg = g_qkv + (size_t)q0 * QKVN + h * HD;
    for (int idx = tid; idx < FBM * (HD / 4); idx += 256) {
        int r  = idx % FBM;
        int dq = idx / FBM;            // 0..19
        float4 v = *(const float4*)&qg[(size_t)r * QKVN + 4 * dq];
        Qt[(4 * dq + 0) * FRP + r] = v.x * INV_SCALE;
        Qt[(4 * dq + 1) * FRP + r] = v.y * INV_SCALE;
        Qt[(4 * dq + 2) * FRP + r] = v.z * INV_SCALE;
        Qt[(4 * dq + 3) * FRP + r] = v.w * INV_SCALE;
    }

    float o[8][5];
    float m[8], l[8];
    #pragma unroll
    for (int i = 0; i < 8; i++) {
        m[i] = -3.0e38f; l[i] = 0.f;
        #pragma unroll
        for (int j = 0; j < 5; j++) o[i][j] = 0.f;
    }
    __syncthreads();

    for (int kt = 0; kt < SEQ / FBN; kt++) {
        int k0 = kt * FBN;
        const float* kg = g_qkv + (size_t)k0 * QKVN + HIDDEN     + h * HD;
        const float* vg = g_qkv + (size_t)k0 * QKVN + 2 * HIDDEN + h * HD;

        // Kt transposed: c-major map (conflict-free STS)
        for (int idx = tid; idx < FBN * (HD / 4); idx += 256) {
            int c  = idx % FBN;
            int dq = idx / FBN;
            float4 v = *(const float4*)&kg[(size_t)c * QKVN + 4 * dq];
            Kt[(4 * dq + 0) * FRP + c] = v.x;
            Kt[(4 * dq + 1) * FRP + c] = v.y;
            Kt[(4 * dq + 2) * FRP + c] = v.z;
            Kt[(4 * dq + 3) * FRP + c] = v.w;
        }
        // Vs row-major: d-major map (coalesced gmem, vector STS)
        for (int idx = tid; idx < FBN * (HD / 4); idx += 256) {
            int c  = idx / (HD / 4);
            int dq = idx % (HD / 4);
            *(float4*)&Vs[c * FVP + 4 * dq] =
                *(const float4*)&vg[(size_t)c * QKVN + 4 * dq];
        }
        __syncthreads();

        // ---- S = Q K^T (8x8 per thread) ----
        float acc[8][8];
        #pragma unroll
        for (int i = 0; i < 8; i++)
            #pragma unroll
            for (int j = 0; j < 8; j++) acc[i][j] = 0.f;

        #pragma unroll 2
        for (int k = 0; k < HD; k++) {
            float qa[8], kb[8];
            *(float4*)&qa[0] = *(const float4*)&Qt[k * FRP + 8 * tr];
            *(float4*)&qa[4] = *(const float4*)&Qt[k * FRP + 8 * tr + 4];
            *(float4*)&kb[0] = *(const float4*)&Kt[k * FRP + 8 * tc];
            *(float4*)&kb[4] = *(const float4*)&Kt[k * FRP + 8 * tc + 4];
            #pragma unroll
            for (int i = 0; i < 8; i++)
                #pragma unroll
                for (int j = 0; j < 8; j++)
                    acc[i][j] = fmaf(qa[i], kb[j], acc[i][j]);
        }

        // ---- online softmax per row (16-lane row group) ----
        #pragma unroll
        for (int i = 0; i < 8; i++) {
            float rmax = acc[i][0];
            #pragma unroll
            for (int j = 1; j < 8; j++) rmax = fmaxf(rmax, acc[i][j]);
            #pragma unroll
            for (int w = 1; w < 16; w <<= 1)
                rmax = fmaxf(rmax, __shfl_xor_sync(0xffffffffu, rmax, w));
            float mn    = fmaxf(m[i], rmax);
            float alpha = __expf(m[i] - mn);
            float p[8];
            float rs = 0.f;
            #pragma unroll
            for (int j = 0; j < 8; j++) {
                p[j] = __expf(acc[i][j] - mn);
                rs += p[j];
            }
            *(float4*)&Ss[(8 * tr + i) * FBN + 8 * tc]     = *(float4*)&p[0];
            *(float4*)&Ss[(8 * tr + i) * FBN + 8 * tc + 4] = *(float4*)&p[4];
            #pragma unroll
            for (int w = 1; w < 16; w <<= 1)
                rs += __shfl_xor_sync(0xffffffffu, rs, w);
            l[i] = l[i] * alpha + rs;
            m[i] = mn;
            #pragma unroll
            for (int j = 0; j < 5; j++) o[i][j] *= alpha;
        }
        __syncwarp();   // Ss rows written/read by same half-warp only

        // ---- O += P V ----
        #pragma unroll 2
        for (int c = 0; c < FBN; c++) {
            float vj[5];
            #pragma unroll
            for (int j = 0; j < 5; j++) vj[j] = Vs[c * FVP + 5 * tc + j];
            #pragma unroll
            for (int i = 0; i < 8; i++) {
                float p = Ss[(8 * tr + i) * FBN + c];   // broadcast load
                #pragma unroll
                for (int j = 0; j < 5; j++)
                    o[i][j] = fmaf(p, vj[j], o[i][j]);
            }
        }
        __syncthreads();   // before next tile overwrites Kt/Vs
    }

    // ---- epilogue ----
    #pragma unroll
    for (int i = 0; i < 8; i++) {
        float inv_l = 1.0f / l[i];
        size_t row = (size_t)(q0 + 8 * tr + i);
        #pragma unroll
        for (int j = 0; j < 5; j++)
            g_attn[row * HIDDEN + h * HD + 5 * tc + j] = o[i][j] * inv_l;
    }
}

// =====================================================================
extern "C" void kernel_launch(void* const* d_in, const int* in_sizes, int n_in,
                              void* d_out, int out_size)
{
    const float* x      = (const float*)d_in[0];
    const float* cosE   = (const float*)d_in[1];
    const float* sinE   = (const float*)d_in[2];
    const float* w_qkv  = (const float*)d_in[3];
    const float* b_qkv  = (const float*)d_in[4];
    const float* w_proj = (const float*)d_in[5];
    const float* b_proj = (const float*)d_in[6];
    float*       out    = (float*)d_out;

    float *qkv, *attn;
    cudaGetSymbolAddress((void**)&qkv,  g_qkv);
    cudaGetSymbolAddress((void**)&attn, g_attn);

    cudaFuncSetAttribute(flash_attn_kernel,
                         cudaFuncAttributeMaxDynamicSharedMemorySize,
                         FA2_SMEM_BYTES);

    // 1) QKV GEMM : [4096,1280] @ [1280,3840] + bias
    sgemm_bias<<<dim3(QKVN / 128, SEQ / 128), 256>>>(
        x, w_qkv, b_qkv, qkv, SEQ, QKVN, HIDDEN);

    // 2) RoPE on Q and K
    {
        int tot = 2 * SEQ * NH * (HD / 2);
        rope_kernel<<<(tot + 255) / 256, 256>>>(cosE, sinE);
    }

    // 3) flash attention (BM=BN=128)
    flash_attn_kernel<<<dim3(SEQ / FBM, NH), 256, FA2_SMEM_BYTES>>>();

    // 4) output projection : [4096,1280] @ [1280,1280] + bias
    sgemm_bias<<<dim3(HIDDEN / 128, SEQ / 128), 256>>>(
        attn, w_proj, b_proj, out, SEQ, HIDDEN, HIDDEN);
}

// round 5
// speedup vs baseline: 1.7513x; 1.7513x over previous
#include <cuda_runtime.h>
#include <math.h>
#include <stdint.h>

#define SEQ    4096
#define NH     16
#define HD     80
#define HIDDEN 1280
#define QKVN   3840
#define INV_SCALE 0.11180339887498948f   // 1/sqrt(80)

// -------- scratch (no allocation allowed -> __device__ globals) --------
__device__ float g_qkv [SEQ * QKVN];    // 62.9 MB : [seq][3*hidden]
__device__ float g_attn[SEQ * HIDDEN];  // 21.0 MB : attention output

// =====================================================================
// SGEMM: C[M,N] = A[M,K] @ B[K,N] + bias[N]   (fp32, 128x128x8)
// =====================================================================
__global__ void __launch_bounds__(256)
sgemm_bias(const float* __restrict__ A, const float* __restrict__ B,
           const float* __restrict__ bias, float* __restrict__ C,
           int M, int N, int K)
{
    const int BM = 128, BN = 128, BK = 8, TM = 8, TN = 8;
    __shared__ float As[BK][BM];
    __shared__ float Bs[BK][BN];

    int tid = threadIdx.x;
    int tx = tid % 16;
    int ty = tid / 16;
    int bx = blockIdx.x, by = blockIdx.y;

    const float* Ab = A + (size_t)by * BM * K;
    const float* Bb = B + (size_t)bx * BN;

    int arow = tid >> 1;
    int acol = (tid & 1) * 4;
    int brow = tid >> 5;
    int bcol = (tid & 31) * 4;

    float acc[TM][TN];
    #pragma unroll
    for (int i = 0; i < TM; i++)
        #pragma unroll
        for (int j = 0; j < TN; j++) acc[i][j] = 0.f;

    for (int k0 = 0; k0 < K; k0 += BK) {
        float4 a4 = *(const float4*)&Ab[(size_t)arow * K + k0 + acol];
        As[acol + 0][arow] = a4.x;
        As[acol + 1][arow] = a4.y;
        As[acol + 2][arow] = a4.z;
        As[acol + 3][arow] = a4.w;
        float4 b4 = *(const float4*)&Bb[(size_t)(k0 + brow) * N + bcol];
        *(float4*)&Bs[brow][bcol] = b4;
        __syncthreads();

        #pragma unroll
        for (int k = 0; k < BK; k++) {
            float ra[TM], rb[TN];
            *(float4*)&ra[0] = *(const float4*)&As[k][ty * TM];
            *(float4*)&ra[4] = *(const float4*)&As[k][ty * TM + 4];
            *(float4*)&rb[0] = *(const float4*)&Bs[k][tx * TN];
            *(float4*)&rb[4] = *(const float4*)&Bs[k][tx * TN + 4];
            #pragma unroll
            for (int i = 0; i < TM; i++)
                #pragma unroll
                for (int j = 0; j < TN; j++)
                    acc[i][j] = fmaf(ra[i], rb[j], acc[i][j]);
        }
        __syncthreads();
    }

    #pragma unroll
    for (int i = 0; i < TM; i++) {
        size_t row = (size_t)by * BM + ty * TM + i;
        #pragma unroll
        for (int j = 0; j < TN; j += 4) {
            int col = bx * BN + tx * TN + j;
            float4 c4;
            c4.x = acc[i][j + 0] + bias[col + 0];
            c4.y = acc[i][j + 1] + bias[col + 1];
            c4.z = acc[i][j + 2] + bias[col + 2];
            c4.w = acc[i][j + 3] + bias[col + 3];
            *(float4*)&C[row * N + col] = c4;
        }
    }
}

// =====================================================================
// RoPE in-place on Q and K halves of g_qkv.
// =====================================================================
__global__ void rope_kernel(const float* __restrict__ cosE,
                            const float* __restrict__ sinE)
{
    int idx = blockIdx.x * blockDim.x + threadIdx.x;
    const int TOT = 2 * SEQ * NH * (HD / 2);
    if (idx >= TOT) return;
    int d    = idx % 40;
    int h    = (idx / 40) % NH;
    int s    = (idx / (40 * NH)) % SEQ;
    int part = idx / (40 * NH * SEQ);

    float* p = g_qkv + (size_t)s * QKVN + part * HIDDEN + h * HD;
    float t1 = p[d], t2 = p[d + 40];
    float c1 = cosE[s * HD + d],      s1 = sinE[s * HD + d];
    float c2 = cosE[s * HD + d + 40], s2 = sinE[s * HD + d + 40];
    p[d]      = t1 * c1 - t2 * s1;
    p[d + 40] = t2 * c2 + t1 * s2;
}

// =====================================================================
// TF32 tensor-core flash attention.
// grid=(SEQ/128, NH), 256 threads = 8 warps; each warp owns 16 query rows.
// mma.sync.m16n8k8 tf32. Q fragments register-resident across KV loop.
// Smem: Ks[128][84], Vs[128][88], Ss[128][132] (pads = conflict-free frags).
// =====================================================================
#define PK 84
#define PVp 88
#define PS 132
#define FA_SMEM_BYTES ((128*PK + 128*PVp + 128*PS) * 4)

__device__ __forceinline__ float cvt_tf32(float x) {
    uint32_t u;
    asm("cvt.rna.tf32.f32 %0, %1;" : "=r"(u) : "f"(x));
    return __uint_as_float(u);
}

__device__ __forceinline__ void mma_tf32(float* c,
    uint32_t a0, uint32_t a1, uint32_t a2, uint32_t a3,
    uint32_t b0, uint32_t b1)
{
    asm volatile(
        "mma.sync.aligned.m16n8k8.row.col.f32.tf32.tf32.f32 "
        "{%0,%1,%2,%3}, {%4,%5,%6,%7}, {%8,%9}, {%0,%1,%2,%3};\n"
        : "+f"(c[0]), "+f"(c[1]), "+f"(c[2]), "+f"(c[3])
        : "r"(a0), "r"(a1), "r"(a2), "r"(a3), "r"(b0), "r"(b1));
}

__global__ void __launch_bounds__(256, 1)
flash_attn_tc()
{
    extern __shared__ float sm[];
    float* Ks = sm;                    // [128][PK]
    float* Vs = Ks + 128 * PK;         // [128][PVp]
    float* Ss = Vs + 128 * PVp;        // [128][PS]; also Q staging (pad PK)

    int tid  = threadIdx.x;
    int lane = tid & 31;
    int w    = tid >> 5;               // warp 0..7 -> rows 16w..16w+15
    int g    = lane >> 2;              // group id (row within octet)
    int t    = lane & 3;               // thread in group
    int h    = blockIdx.y;
    int q0   = blockIdx.x * 128;

    // ---- stage Q (scaled + tf32-rounded) into Ss with pad PK ----
    const float* qg = g_qkv + (size_t)q0 * QKVN + h * HD;
    for (int i = tid; i < 128 * 20; i += 256) {
        int r = i / 20, c = i % 20;
        float4 v = *(const float4*)&qg[(size_t)r * QKVN + 4 * c];
        v.x = cvt_tf32(v.x * INV_SCALE);
        v.y = cvt_tf32(v.y * INV_SCALE);
        v.z = cvt_tf32(v.z * INV_SCALE);
        v.w = cvt_tf32(v.w * INV_SCALE);
        *(float4*)&Ss[r * PK + 4 * c] = v;
    }
    __syncthreads();

    // ---- load Q fragments into registers (10 k-steps x 4 regs) ----
    uint32_t qf[10][4];
    {
        int r0 = (16 * w + g) * PK;
        int r1 = (16 * w + g + 8) * PK;
        #pragma unroll
        for (int s = 0; s < 10; s++) {
            qf[s][0] = __float_as_uint(Ss[r0 + 8 * s + t]);
            qf[s][1] = __float_as_uint(Ss[r1 + 8 * s + t]);
            qf[s][2] = __float_as_uint(Ss[r0 + 8 * s + t + 4]);
            qf[s][3] = __float_as_uint(Ss[r1 + 8 * s + t + 4]);
        }
    }

    float o[10][4];
    #pragma unroll
    for (int n = 0; n < 10; n++)
        #pragma unroll
        for (int j = 0; j < 4; j++) o[n][j] = 0.f;
    float m0 = -3.0e38f, m1 = -3.0e38f, l0 = 0.f, l1 = 0.f;

    for (int kt = 0; kt < SEQ / 128; kt++) {
        __syncthreads();   // prev iter done reading Ks/Vs; Q frags loaded
        int k0 = kt * 128;
        const float* kg = g_qkv + (size_t)k0 * QKVN + HIDDEN     + h * HD;
        const float* vg = g_qkv + (size_t)k0 * QKVN + 2 * HIDDEN + h * HD;
        for (int i = tid; i < 128 * 20; i += 256) {
            int r = i / 20, c = i % 20;
            float4 a = *(const float4*)&kg[(size_t)r * QKVN + 4 * c];
            a.x = cvt_tf32(a.x); a.y = cvt_tf32(a.y);
            a.z = cvt_tf32(a.z); a.w = cvt_tf32(a.w);
            *(float4*)&Ks[r * PK + 4 * c] = a;
            float4 b = *(const float4*)&vg[(size_t)r * QKVN + 4 * c];
            b.x = cvt_tf32(b.x); b.y = cvt_tf32(b.y);
            b.z = cvt_tf32(b.z); b.w = cvt_tf32(b.w);
            *(float4*)&Vs[r * PVp + 4 * c] = b;
        }
        __syncthreads();

        // ---- S = Q K^T : 16 n-tiles x 10 k-steps ----
        float sacc[16][4];
        #pragma unroll
        for (int n = 0; n < 16; n++)
            #pragma unroll
            for (int j = 0; j < 4; j++) sacc[n][j] = 0.f;

        #pragma unroll
        for (int s = 0; s < 10; s++) {
            #pragma unroll
            for (int nt = 0; nt < 16; nt++) {
                uint32_t b0 = __float_as_uint(Ks[(8 * nt + g) * PK + 8 * s + t]);
                uint32_t b1 = __float_as_uint(Ks[(8 * nt + g) * PK + 8 * s + t + 4]);
                mma_tf32(sacc[nt], qf[s][0], qf[s][1], qf[s][2], qf[s][3], b0, b1);
            }
        }

        // ---- online softmax (rows g and g+8 of this warp's slab) ----
        float rmax0 = sacc[0][0], rmax1 = sacc[0][2];
        #pragma unroll
        for (int nt = 0; nt < 16; nt++) {
            rmax0 = fmaxf(rmax0, fmaxf(sacc[nt][0], sacc[nt][1]));
            rmax1 = fmaxf(rmax1, fmaxf(sacc[nt][2], sacc[nt][3]));
        }
        rmax0 = fmaxf(rmax0, __shfl_xor_sync(0xffffffffu, rmax0, 1));
        rmax0 = fmaxf(rmax0, __shfl_xor_sync(0xffffffffu, rmax0, 2));
        rmax1 = fmaxf(rmax1, __shfl_xor_sync(0xffffffffu, rmax1, 1));
        rmax1 = fmaxf(rmax1, __shfl_xor_sync(0xffffffffu, rmax1, 2));

        float mn0 = fmaxf(m0, rmax0), mn1 = fmaxf(m1, rmax1);
        float alpha0 = __expf(m0 - mn0), alpha1 = __expf(m1 - mn1);
        m0 = mn0; m1 = mn1;

        float rs0 = 0.f, rs1 = 0.f;
        int pr0 = (16 * w + g) * PS;
        int pr1 = (16 * w + g + 8) * PS;
        #pragma unroll
        for (int nt = 0; nt < 16; nt++) {
            float p0 = __expf(sacc[nt][0] - mn0);
            float p1 = __expf(sacc[nt][1] - mn0);
            float p2 = __expf(sacc[nt][2] - mn1);
            float p3 = __expf(sacc[nt][3] - mn1);
            rs0 += p0 + p1;
            rs1 += p2 + p3;
            float2 u0 = make_float2(cvt_tf32(p0), cvt_tf32(p1));
            float2 u1 = make_float2(cvt_tf32(p2), cvt_tf32(p3));
            *(float2*)&Ss[pr0 + 8 * nt + 2 * t] = u0;
            *(float2*)&Ss[pr1 + 8 * nt + 2 * t] = u1;
        }
        rs0 += __shfl_xor_sync(0xffffffffu, rs0, 1);
        rs0 += __shfl_xor_sync(0xffffffffu, rs0, 2);
        rs1 += __shfl_xor_sync(0xffffffffu, rs1, 1);
        rs1 += __shfl_xor_sync(0xffffffffu, rs1, 2);
        l0 = l0 * alpha0 + rs0;
        l1 = l1 * alpha1 + rs1;

        #pragma unroll
        for (int n = 0; n < 10; n++) {
            o[n][0] *= alpha0; o[n][1] *= alpha0;
            o[n][2] *= alpha1; o[n][3] *= alpha1;
        }
        __syncwarp();   // P slab written/read within this warp only

        // ---- O += P V : 16 k-steps (keys) x 10 n-tiles (dims) ----
        #pragma unroll
        for (int s = 0; s < 16; s++) {
            uint32_t a0 = __float_as_uint(Ss[pr0 + 8 * s + t]);
            uint32_t a1 = __float_as_uint(Ss[pr1 + 8 * s + t]);
            uint32_t a2 = __float_as_uint(Ss[pr0 + 8 * s + t + 4]);
            uint32_t a3 = __float_as_uint(Ss[pr1 + 8 * s + t + 4]);
            #pragma unroll
            for (int nt = 0; nt < 10; nt++) {
                uint32_t b0 = __float_as_uint(Vs[(8 * s + t) * PVp + 8 * nt + g]);
                uint32_t b1 = __float_as_uint(Vs[(8 * s + t + 4) * PVp + 8 * nt + g]);
                mma_tf32(o[nt], a0, a1, a2, a3, b0, b1);
            }
        }
        __syncwarp();   // PV reads of Ss done before next tile's P writes
    }

    // ---- epilogue ----
    float il0 = 1.0f / l0, il1 = 1.0f / l1;
    size_t r0 = (size_t)(q0 + 16 * w + g);
    size_t r1 = r0 + 8;
    float* og0 = g_attn + r0 * HIDDEN + h * HD;
    float* og1 = g_attn + r1 * HIDDEN + h * HD;
    #pragma unroll
    for (int nt = 0; nt < 10; nt++) {
        *(float2*)&og0[8 * nt + 2 * t] = make_float2(o[nt][0] * il0, o[nt][1] * il0);
        *(float2*)&og1[8 * nt + 2 * t] = make_float2(o[nt][2] * il1, o[nt][3] * il1);
    }
}

// =====================================================================
extern "C" void kernel_launch(void* const* d_in, const int* in_sizes, int n_in,
                              void* d_out, int out_size)
{
    const float* x      = (const float*)d_in[0];
    const float* cosE   = (const float*)d_in[1];
    const float* sinE   = (const float*)d_in[2];
    const float* w_qkv  = (const float*)d_in[3];
    const float* b_qkv  = (const float*)d_in[4];
    const float* w_proj = (const float*)d_in[5];
    const float* b_proj = (const float*)d_in[6];
    float*       out    = (float*)d_out;

    float *qkv, *attn;
    cudaGetSymbolAddress((void**)&qkv,  g_qkv);
    cudaGetSymbolAddress((void**)&attn, g_attn);

    cudaFuncSetAttribute(flash_attn_tc,
                         cudaFuncAttributeMaxDynamicSharedMemorySize,
                         FA_SMEM_BYTES);

    // 1) QKV GEMM : [4096,1280] @ [1280,3840] + bias
    sgemm_bias<<<dim3(QKVN / 128, SEQ / 128), 256>>>(
        x, w_qkv, b_qkv, qkv, SEQ, QKVN, HIDDEN);

    // 2) RoPE on Q and K
    {
        int tot = 2 * SEQ * NH * (HD / 2);
        rope_kernel<<<(tot + 255) / 256, 256>>>(cosE, sinE);
    }

    // 3) tensor-core flash attention
    flash_attn_tc<<<dim3(SEQ / 128, NH), 256, FA_SMEM_BYTES>>>();

    // 4) output projection : [4096,1280] @ [1280,1280] + bias
    sgemm_bias<<<dim3(HIDDEN / 128, SEQ / 128), 256>>>(
        attn, w_proj, b_proj, out, SEQ, HIDDEN, HIDDEN);
}